// round 11
// baseline (speedup 1.0000x reference)
#include <cuda_runtime.h>
#include <cstdint>

#define SCORE_THRESH 0.05f
#define IOU_THRESH   0.5f
#define KTOP 1000
#define KPAD 1024
#define MAXDET 100
#define MAX_A (1 << 18)
#define NBLK 148
#define NTHR 1024
#define DSMEM_NMS 131072

// ---------------- device scratch ----------------
__device__ __align__(16) unsigned g_key[MAX_A];
__device__ __align__(16) unsigned long long g_ties64[MAX_A];
__device__ unsigned long long  g_cand[KPAD];
__device__ unsigned            g_hist0[2048];
__device__ unsigned            g_hist1[2048];
__device__ int                 g_candCount;
__device__ int                 g_tieCount;
__device__ __align__(16) unsigned g_maskR[KPAD * 32];
__device__ float               g_rscore[KPAD];
__device__ unsigned            g_ridx[KPAD];
__device__ __align__(16) float g_rbox[KPAD * 4];

__device__ __forceinline__ unsigned f2key(float f) {
    unsigned b = __float_as_uint(f);
    return (b & 0x80000000u) ? ~b : (b | 0x80000000u);
}
__device__ __forceinline__ float key2f(unsigned k) {
    unsigned b = (k & 0x80000000u) ? (k ^ 0x80000000u) : ~k;
    return __uint_as_float(b);
}

// ======= K1: per-anchor score + pass-0 histogram (proven 15.1us) ===========
__global__ void __launch_bounds__(256, 8)
k_score(const float* __restrict__ cls, int A, int C) {
    __shared__ unsigned sh[2048];
    for (int i = threadIdx.x; i < 2048; i += 256) sh[i] = 0;
    __syncthreads();
    int lane = threadIdx.x & 31;
    int gw = blockIdx.x * 8 + (threadIdx.x >> 5);
    int nw = gridDim.x * 8;
    if (C == 80) {
        const float4* p = (const float4*)cls;
        for (int a0 = gw * 8; a0 < A; a0 += nw * 8) {
            float m[8];
            #pragma unroll
            for (int r = 0; r < 8; ++r) m[r] = 0.0f;     // scores >= 0
            if (lane < 20) {
                #pragma unroll
                for (int r = 0; r < 8; ++r) {
                    int a = a0 + r;
                    if (a < A) {
                        float4 v = p[(size_t)a * 20 + lane];
                        m[r] = fmaxf(fmaxf(v.x, v.y), fmaxf(v.z, v.w));
                    }
                }
            }
            #pragma unroll
            for (int r = 0; r < 8; ++r) {
                unsigned u = __reduce_max_sync(0xFFFFFFFFu, __float_as_uint(m[r]));
                m[r] = __uint_as_float(u);
            }
            if (lane < 8) {
                float mv;
                switch (lane) {
                    case 0: mv = m[0]; break;
                    case 1: mv = m[1]; break;
                    case 2: mv = m[2]; break;
                    case 3: mv = m[3]; break;
                    case 4: mv = m[4]; break;
                    case 5: mv = m[5]; break;
                    case 6: mv = m[6]; break;
                    default: mv = m[7]; break;
                }
                int a = a0 + lane;
                bool valid = (a < A);
                unsigned k = f2key(mv > SCORE_THRESH ? mv : -1.0f);
                if (valid) g_key[a] = k;
                unsigned bin = valid ? (k >> 21) : (2048u + (unsigned)lane);
                unsigned mm = __match_any_sync(0xFFu, bin);
                if (valid && lane == (__ffs(mm) - 1))
                    atomicAdd(&sh[bin], (unsigned)__popc(mm));
            }
        }
    } else {
        for (int a = gw; a < A; a += nw) {
            float mm2 = -3.402823466e38f;
            const float* row = cls + (size_t)a * C;
            for (int c = lane; c < C; c += 32) mm2 = fmaxf(mm2, row[c]);
            #pragma unroll
            for (int o = 16; o; o >>= 1) mm2 = fmaxf(mm2, __shfl_down_sync(0xFFFFFFFFu, mm2, o));
            if (lane == 0) {
                unsigned k = f2key(mm2 > SCORE_THRESH ? mm2 : -1.0f);
                g_key[a] = k;
                atomicAdd(&sh[k >> 21], 1u);
            }
        }
    }
    __syncthreads();
    for (int i = threadIdx.x; i < 2048; i += 256) {
        unsigned v = sh[i];
        if (v) atomicAdd(&g_hist0[i], v);
    }
}

// block-local radix select over a global histogram (redundant per block)
__device__ void block_select(const unsigned* hist, unsigned krem,
                             unsigned* wsm, int* psel,
                             unsigned* pdig, unsigned* pkrem) {
    int t = threadIdx.x, lane = t & 31, w = t >> 5;
    unsigned c0 = hist[2 * t];
    unsigned c1 = hist[2 * t + 1];
    unsigned tot = c0 + c1;
    if (t == 0) *psel = -1;
    unsigned s = tot;
    #pragma unroll
    for (int off = 1; off < 32; off <<= 1) {
        unsigned v = __shfl_down_sync(0xFFFFFFFFu, s, off);
        if (lane + off < 32) s += v;
    }
    if (lane == 0) wsm[w] = s;
    __syncthreads();
    if (t < 32) {
        unsigned wv = wsm[t];
        unsigned ws = wv;
        #pragma unroll
        for (int off = 1; off < 32; off <<= 1) {
            unsigned v = __shfl_down_sync(0xFFFFFFFFu, ws, off);
            if (t + off < 32) ws += v;
        }
        wsm[t] = ws - wv;
    }
    __syncthreads();
    unsigned suffExcl = wsm[w] + (s - tot);
    int best = -1; unsigned accAt = 0, cntAt = 0;
    unsigned acc = suffExcl + c1;
    if (acc >= krem) { best = 2 * t + 1; accAt = acc; cntAt = c1; }
    else { acc += c0; if (acc >= krem) { best = 2 * t; accAt = acc; cntAt = c0; } }
    if (best >= 0) atomicMax(psel, best);
    __syncthreads();
    if (best >= 0 && best == *psel) {
        *pdig = (unsigned)best;
        *pkrem = krem - (accAt - cntAt);
    }
    __syncthreads();
}

// ======= K2: select0 + sweep -> hist1 (11 bits within bin0) ================
__global__ void __launch_bounds__(NTHR, 1)
k_sweep1(int A) {
    __shared__ unsigned s_wsm[32];
    __shared__ int s_sel;
    __shared__ unsigned s_dig, s_krem;
    __shared__ unsigned sh[2048];
    int tid = threadIdx.x, bid = blockIdx.x;
    block_select(g_hist0, KTOP, s_wsm, &s_sel, &s_dig, &s_krem);
    unsigned pref0 = s_dig;
    for (int i = tid; i < 2048; i += NTHR) sh[i] = 0;
    __syncthreads();
    int A4 = A >> 2, Atail = A4 << 2;
    const uint4* kp = (const uint4*)g_key;
    for (int i = bid * NTHR + tid; i < A4; i += NBLK * NTHR) {
        uint4 k = kp[i];
        if ((k.x >> 21) == pref0) atomicAdd(&sh[(k.x >> 10) & 0x7FFu], 1u);
        if ((k.y >> 21) == pref0) atomicAdd(&sh[(k.y >> 10) & 0x7FFu], 1u);
        if ((k.z >> 21) == pref0) atomicAdd(&sh[(k.z >> 10) & 0x7FFu], 1u);
        if ((k.w >> 21) == pref0) atomicAdd(&sh[(k.w >> 10) & 0x7FFu], 1u);
    }
    if (bid == 0) {
        for (int a = Atail + tid; a < A; a += NTHR) {
            unsigned k = g_key[a];
            if ((k >> 21) == pref0) atomicAdd(&sh[(k >> 10) & 0x7FFu], 1u);
        }
    }
    __syncthreads();
    for (int i = tid; i < 2048; i += NTHR) {
        unsigned v = sh[i];
        if (v) atomicAdd(&g_hist1[i], v);
    }
}

// ======= K3: select0+1 -> 22-bit pivot; compact cands + u64 ties ===========
__global__ void __launch_bounds__(NTHR, 1)
k_compact(int A) {
    __shared__ unsigned s_wsm[32];
    __shared__ int s_sel;
    __shared__ unsigned s_dig, s_krem;
    int tid = threadIdx.x, bid = blockIdx.x;
    block_select(g_hist0, KTOP, s_wsm, &s_sel, &s_dig, &s_krem);
    unsigned pref0 = s_dig, krem1 = s_krem;
    block_select(g_hist1, krem1, s_wsm, &s_sel, &s_dig, &s_krem);
    unsigned pivot22 = (pref0 << 11) | s_dig;
    int A4 = A >> 2, Atail = A4 << 2;
    const uint4* kp = (const uint4*)g_key;
    for (int i = bid * NTHR + tid; i < A4; i += NBLK * NTHR) {
        uint4 kv = kp[i];
        unsigned base = (unsigned)(i << 2);
        #pragma unroll
        for (int c = 0; c < 4; ++c) {
            unsigned k = (c == 0) ? kv.x : (c == 1) ? kv.y : (c == 2) ? kv.z : kv.w;
            unsigned kk = k >> 10;
            if (kk > pivot22) {
                int p = atomicAdd(&g_candCount, 1);
                g_cand[p] = ((unsigned long long)k << 32) | (0xFFFFFFFFu - (base + c));
            } else if (kk == pivot22) {
                int t2 = atomicAdd(&g_tieCount, 1);
                g_ties64[t2] = ((unsigned long long)k << 32) | (0xFFFFFFFFu - (base + c));
            }
        }
    }
    if (bid == 0) {
        for (int a = Atail + tid; a < A; a += NTHR) {
            unsigned k = g_key[a];
            unsigned kk = k >> 10;
            if (kk > pivot22) {
                int p = atomicAdd(&g_candCount, 1);
                g_cand[p] = ((unsigned long long)k << 32) | (0xFFFFFFFFu - (unsigned)a);
            } else if (kk == pivot22) {
                int t2 = atomicAdd(&g_tieCount, 1);
                g_ties64[t2] = ((unsigned long long)k << 32) | (0xFFFFFFFFu - (unsigned)a);
            }
        }
    }
}

// ======= K4 (1 block): tie-fill + bitonic sort + decode + cleanup ==========
__global__ void __launch_bounds__(NTHR, 1)
k_prep(const float* __restrict__ reg, const float* __restrict__ anc,
       const int* __restrict__ pih, const int* __restrict__ piw) {
    __shared__ unsigned long long scand[KPAD];    // 8KB
    __shared__ unsigned long long sties[2048];    // 16KB
    int tid = threadIdx.x;
    int CA = g_candCount, T = g_tieCount;
    int need = KTOP - CA;
    scand[tid] = (tid < CA) ? g_cand[tid]
               : ((tid >= KTOP) ? (unsigned long long)(KPAD - tid) : 0ULL);
    if (need > 0) {
        if (T <= 2048) {
            if (tid < T) sties[tid] = g_ties64[tid];
            if (tid + 1024 < T) sties[tid + 1024] = g_ties64[tid + 1024];
            __syncthreads();
            for (int t = tid; t < T; t += NTHR) {
                unsigned long long mine = sties[t];
                int rank = 0;
                for (int i = 0; i < T; ++i) rank += (sties[i] > mine);
                if (rank < need) scand[CA + rank] = mine;
            }
        } else {
            // correct-but-slow fallback: sequential max extraction
            unsigned long long prev = ~0ULL;
            for (int r2 = 0; r2 < need; ++r2) {
                unsigned long long lm = 0ULL;
                for (int i = tid; i < T; i += NTHR) {
                    unsigned long long v = g_ties64[i];
                    if (v < prev && v > lm) lm = v;
                }
                sties[tid] = lm;
                __syncthreads();
                for (int st = 512; st; st >>= 1) {
                    if (tid < st && sties[tid + st] > sties[tid]) sties[tid] = sties[tid + st];
                    __syncthreads();
                }
                prev = sties[0];
                if (tid == 0) scand[CA + r2] = prev;
                __syncthreads();
            }
        }
    }
    __syncthreads();
    // bitonic sort descending (score desc, index asc) -> rank == position
    for (int k = 2; k <= 1024; k <<= 1)
        for (int j = k >> 1; j > 0; j >>= 1) {
            int ixj = tid ^ j;
            if (ixj > tid) {
                unsigned long long a = scand[tid], b = scand[ixj];
                bool up = ((tid & k) == 0);
                if (up ? (a < b) : (a > b)) { scand[tid] = b; scand[ixj] = a; }
            }
            __syncthreads();
        }
    unsigned long long ck = scand[tid];
    float score; float4 box; unsigned idx = 0;
    if (ck >= (1ULL << 32)) {
        unsigned key = (unsigned)(ck >> 32);
        idx = 0xFFFFFFFFu - (unsigned)(ck & 0xFFFFFFFFu);
        score = key2f(key);
        float4 a4 = ((const float4*)anc)[idx];
        float4 r4 = ((const float4*)reg)[idx];
        float aw = a4.z - a4.x, ah = a4.w - a4.y;
        float acx = a4.x + 0.5f * aw, acy = a4.y + 0.5f * ah;
        float pcx = acx + (r4.x * 0.1f) * aw;
        float pcy = acy + (r4.y * 0.1f) * ah;
        float pw = expf(r4.z * 0.2f) * aw;
        float ph = expf(r4.w * 0.2f) * ah;
        float W = (float)(*piw);
        float H = (float)(*pih);
        box.x = fminf(fmaxf(pcx - 0.5f * pw, 0.f), W);
        box.y = fminf(fmaxf(pcy - 0.5f * ph, 0.f), H);
        box.z = fminf(fmaxf(pcx + 0.5f * pw, 0.f), W);
        box.w = fminf(fmaxf(pcy + 0.5f * ph, 0.f), H);
    } else {
        score = -1.0f;
        box.x = box.y = box.z = box.w = 0.f;
    }
    g_rscore[tid] = score;
    g_ridx[tid] = idx;
    ((float4*)g_rbox)[tid] = box;
    // cleanup for next graph replay (single block: race-free)
    for (int i = tid; i < 2048; i += NTHR) { g_hist0[i] = 0; g_hist1[i] = 0; }
    if (tid == 0) { g_candCount = 0; g_tieCount = 0; }
}

// ======= K5: triangle IoU suppression mask (rank space) ====================
__global__ void __launch_bounds__(NTHR, 1)
k_mask() {
    __shared__ float4 sbox[KPAD];
    __shared__ float  sarea[KPAD];
    int tid = threadIdx.x, bid = blockIdx.x;
    float4 b0 = ((const float4*)g_rbox)[tid];
    sbox[tid] = b0;
    sarea[tid] = fmaxf(b0.z - b0.x, 0.f) * fmaxf(b0.w - b0.y, 0.f);
    __syncthreads();
    float4 cb = sbox[tid];
    float  ca = sarea[tid];
    for (int r = bid; r < KPAD; r += NBLK) {
        bool sup = false;
        if (tid > r) {
            float4 rb = sbox[r];
            float  ra = sarea[r];
            float xx1 = fmaxf(rb.x, cb.x);
            float yy1 = fmaxf(rb.y, cb.y);
            float xx2 = fminf(rb.z, cb.z);
            float yy2 = fminf(rb.w, cb.w);
            float inter = fmaxf(xx2 - xx1, 0.f) * fmaxf(yy2 - yy1, 0.f);
            float denom = ra + ca - inter + 1e-8f;
            sup = inter > IOU_THRESH * denom;
        }
        unsigned ball = __ballot_sync(0xFFFFFFFFu, sup);
        if ((tid & 31) == 0) g_maskR[r * 32 + (tid >> 5)] = ball;
    }
}

// ======= K6 (1 block): NMS scan + final outputs ============================
__global__ void __launch_bounds__(NTHR, 1)
k_nms(const float* __restrict__ cls, float* __restrict__ out, int C) {
    extern __shared__ unsigned char dsm[];
    __shared__ int s_dc;
    __shared__ int s_det[128];
    int tid = threadIdx.x;
    unsigned* smask = (unsigned*)dsm;
    {
        const uint4* gm = (const uint4*)g_maskR;
        uint4* sm4 = (uint4*)smask;
        for (int i = tid; i < KPAD * 8; i += NTHR) sm4[i] = gm[i];
    }
    int myvalid = (g_rscore[tid] > SCORE_THRESH) ? 1 : 0;
    int nvalid = __syncthreads_count(myvalid);   // valid = rank prefix
    if (tid < 32) {
        int base = tid * 32;
        unsigned alive;
        if (nvalid >= base + 32)      alive = 0xFFFFFFFFu;
        else if (nvalid <= base)      alive = 0u;
        else                          alive = (1u << (nvalid - base)) - 1u;
        unsigned rem = 0;
        int dc = 0;
        while (dc < MAXDET) {
            unsigned av = alive & ~rem;
            unsigned ball = __ballot_sync(0xFFFFFFFFu, av != 0u);
            if (!ball) break;
            int grp = __ffs(ball) - 1;
            unsigned gav = __shfl_sync(0xFFFFFFFFu, av, grp);
            int b = __ffs(gav) - 1;
            int rank = (grp << 5) + b;
            if (tid == 0) s_det[dc] = rank;
            dc++;
            if (tid == grp) alive &= ~(1u << b);
            rem |= smask[rank * 32 + tid];
        }
        if (tid == 0) s_dc = dc;
    }
    __syncthreads();
    int dc = s_dc;
    int lane = tid & 31;
    int w = tid >> 5;
    for (int d = w; d < MAXDET; d += 32) {
        if (d < dc) {
            int rank = s_det[d];
            unsigned idx = g_ridx[rank];
            const float* row = cls + (size_t)idx * C;
            float bv = -3.402823466e38f; int bi = 0;
            for (int c = lane; c < C; c += 32) {
                float v = row[c];
                if (v > bv) { bv = v; bi = c; }
            }
            #pragma unroll
            for (int o = 16; o; o >>= 1) {
                float ov = __shfl_down_sync(0xFFFFFFFFu, bv, o);
                int   oi = __shfl_down_sync(0xFFFFFFFFu, bi, o);
                if (ov > bv || (ov == bv && oi < bi)) { bv = ov; bi = oi; }
            }
            if (lane == 0) {
                out[d] = g_rscore[rank];
                out[100 + d] = (float)bi;
                out[200 + 4 * d + 0] = g_rbox[4 * rank + 0];
                out[200 + 4 * d + 1] = g_rbox[4 * rank + 1];
                out[200 + 4 * d + 2] = g_rbox[4 * rank + 2];
                out[200 + 4 * d + 3] = g_rbox[4 * rank + 3];
            }
        } else if (lane == 0) {
            out[d] = 0.0f;
            out[100 + d] = -1.0f;
            out[200 + 4 * d + 0] = 0.0f; out[200 + 4 * d + 1] = 0.0f;
            out[200 + 4 * d + 2] = 0.0f; out[200 + 4 * d + 3] = 0.0f;
        }
    }
}

// ---------------- host launcher ----------------
extern "C" void kernel_launch(void* const* d_in, const int* in_sizes, int n_in,
                              void* d_out, int out_size) {
    const float* cls = (const float*)d_in[0];
    const float* reg = (const float*)d_in[1];
    const float* anc = (const float*)d_in[2];
    const int* ih = (const int*)d_in[3];
    const int* iw = (const int*)d_in[4];

    int A = in_sizes[1] / 4;
    int C = (A > 0) ? (in_sizes[0] / A) : 80;
    float* out = (float*)d_out;
    (void)out_size; (void)n_in;

    cudaFuncSetAttribute(k_nms, cudaFuncAttributeMaxDynamicSharedMemorySize, DSMEM_NMS);

    k_score<<<1184, 256>>>(cls, A, C);
    k_sweep1<<<NBLK, NTHR>>>(A);
    k_compact<<<NBLK, NTHR>>>(A);
    k_prep<<<1, NTHR>>>(reg, anc, ih, iw);
    k_mask<<<NBLK, NTHR>>>();
    k_nms<<<1, NTHR, DSMEM_NMS>>>(cls, out, C);
}

// round 12
// speedup vs baseline: 1.4917x; 1.4917x over previous
#include <cuda_runtime.h>
#include <cstdint>

#define SCORE_THRESH 0.05f
#define IOU_THRESH   0.5f
#define KTOP 1000
#define KPAD 1024
#define MAXDET 100
#define MAX_A (1 << 18)
#define NBLK 148
#define NTHR 1024
#define DSMEM_NMS 131072

// ---------------- device scratch ----------------
__device__ __align__(16) unsigned g_key[MAX_A];
__device__ unsigned            g_ties[MAX_A];
__device__ unsigned long long  g_cand[KPAD];
__device__ unsigned            g_hist0[2048];
__device__ unsigned            g_hist1[2048];
__device__ unsigned            g_hist2[1024];
__device__ int                 g_candCount;
__device__ int                 g_tieCount;
__device__ __align__(16) unsigned g_maskR[KPAD * 32];
__device__ float               g_rscore[KPAD];
__device__ unsigned            g_ridx[KPAD];
__device__ __align__(16) float g_rbox[KPAD * 4];

__device__ __forceinline__ unsigned f2key(float f) {
    unsigned b = __float_as_uint(f);
    return (b & 0x80000000u) ? ~b : (b | 0x80000000u);
}
__device__ __forceinline__ float key2f(unsigned k) {
    unsigned b = (k & 0x80000000u) ? (k ^ 0x80000000u) : ~k;
    return __uint_as_float(b);
}

// ======= K1: per-anchor score + pass-0 histogram (proven 15.1us) ===========
__global__ void __launch_bounds__(256, 8)
k_score(const float* __restrict__ cls, int A, int C) {
    __shared__ unsigned sh[2048];
    for (int i = threadIdx.x; i < 2048; i += 256) sh[i] = 0;
    __syncthreads();
    int lane = threadIdx.x & 31;
    int gw = blockIdx.x * 8 + (threadIdx.x >> 5);
    int nw = gridDim.x * 8;
    if (C == 80) {
        const float4* p = (const float4*)cls;
        for (int a0 = gw * 8; a0 < A; a0 += nw * 8) {
            float m[8];
            #pragma unroll
            for (int r = 0; r < 8; ++r) m[r] = 0.0f;     // scores >= 0
            if (lane < 20) {
                #pragma unroll
                for (int r = 0; r < 8; ++r) {
                    int a = a0 + r;
                    if (a < A) {
                        float4 v = p[(size_t)a * 20 + lane];
                        m[r] = fmaxf(fmaxf(v.x, v.y), fmaxf(v.z, v.w));
                    }
                }
            }
            #pragma unroll
            for (int r = 0; r < 8; ++r) {
                unsigned u = __reduce_max_sync(0xFFFFFFFFu, __float_as_uint(m[r]));
                m[r] = __uint_as_float(u);
            }
            if (lane < 8) {
                float mv;
                switch (lane) {
                    case 0: mv = m[0]; break;
                    case 1: mv = m[1]; break;
                    case 2: mv = m[2]; break;
                    case 3: mv = m[3]; break;
                    case 4: mv = m[4]; break;
                    case 5: mv = m[5]; break;
                    case 6: mv = m[6]; break;
                    default: mv = m[7]; break;
                }
                int a = a0 + lane;
                bool valid = (a < A);
                unsigned k = f2key(mv > SCORE_THRESH ? mv : -1.0f);
                if (valid) g_key[a] = k;
                unsigned bin = valid ? (k >> 21) : (2048u + (unsigned)lane);
                unsigned mm = __match_any_sync(0xFFu, bin);
                if (valid && lane == (__ffs(mm) - 1))
                    atomicAdd(&sh[bin], (unsigned)__popc(mm));
            }
        }
    } else {
        for (int a = gw; a < A; a += nw) {
            float mm2 = -3.402823466e38f;
            const float* row = cls + (size_t)a * C;
            for (int c = lane; c < C; c += 32) mm2 = fmaxf(mm2, row[c]);
            #pragma unroll
            for (int o = 16; o; o >>= 1) mm2 = fmaxf(mm2, __shfl_down_sync(0xFFFFFFFFu, mm2, o));
            if (lane == 0) {
                unsigned k = f2key(mm2 > SCORE_THRESH ? mm2 : -1.0f);
                g_key[a] = k;
                atomicAdd(&sh[k >> 21], 1u);
            }
        }
    }
    __syncthreads();
    for (int i = threadIdx.x; i < 2048; i += 256) {
        unsigned v = sh[i];
        if (v) atomicAdd(&g_hist0[i], v);
    }
}

// block-local radix select over global histogram (redundant; 3 barriers)
__device__ void block_select(const unsigned* hist, int bins, unsigned krem,
                             unsigned* wsm, int* psel,
                             unsigned* pdig, unsigned* pkrem) {
    int t = threadIdx.x, lane = t & 31, w = t >> 5;
    int per = bins >> 10;
    unsigned c0 = hist[t * per];
    unsigned c1 = (per == 2) ? hist[t * per + 1] : 0u;
    unsigned tot = c0 + c1;
    if (t == 0) *psel = -1;
    unsigned s = tot;
    #pragma unroll
    for (int off = 1; off < 32; off <<= 1) {
        unsigned v = __shfl_down_sync(0xFFFFFFFFu, s, off);
        if (lane + off < 32) s += v;
    }
    if (lane == 0) wsm[w] = s;
    __syncthreads();
    if (t < 32) {
        unsigned wv = wsm[t];
        unsigned ws = wv;
        #pragma unroll
        for (int off = 1; off < 32; off <<= 1) {
            unsigned v = __shfl_down_sync(0xFFFFFFFFu, ws, off);
            if (t + off < 32) ws += v;
        }
        wsm[t] = ws - wv;
    }
    __syncthreads();
    unsigned suffExcl = wsm[w] + (s - tot);
    int best = -1; unsigned accAt = 0, cntAt = 0;
    unsigned acc = suffExcl;
    if (per == 2) {
        acc += c1;
        if (acc >= krem) { best = 2 * t + 1; accAt = acc; cntAt = c1; }
        else { acc += c0; if (acc >= krem) { best = 2 * t; accAt = acc; cntAt = c0; } }
    } else {
        acc += c0;
        if (acc >= krem) { best = t; accAt = acc; cntAt = c0; }
    }
    if (best >= 0) atomicMax(psel, best);
    __syncthreads();
    if (best >= 0 && best == *psel) {
        *pdig = (unsigned)best;
        *pkrem = krem - (accAt - cntAt);
    }
    __syncthreads();
}

// ======= K2: select0 + sweep -> hist1 (next 11 bits within bin0) ===========
__global__ void __launch_bounds__(NTHR, 1)
k_sweep1(int A) {
    __shared__ unsigned s_wsm[32];
    __shared__ int s_sel;
    __shared__ unsigned s_dig, s_krem;
    __shared__ unsigned sh[2048];
    int tid = threadIdx.x, bid = blockIdx.x;
    block_select(g_hist0, 2048, KTOP, s_wsm, &s_sel, &s_dig, &s_krem);
    unsigned pref0 = s_dig;
    for (int i = tid; i < 2048; i += NTHR) sh[i] = 0;
    __syncthreads();
    int A4 = A >> 2, Atail = A4 << 2;
    const uint4* kp = (const uint4*)g_key;
    for (int i = bid * NTHR + tid; i < A4; i += NBLK * NTHR) {
        uint4 k = kp[i];
        if ((k.x >> 21) == pref0) atomicAdd(&sh[(k.x >> 10) & 0x7FFu], 1u);
        if ((k.y >> 21) == pref0) atomicAdd(&sh[(k.y >> 10) & 0x7FFu], 1u);
        if ((k.z >> 21) == pref0) atomicAdd(&sh[(k.z >> 10) & 0x7FFu], 1u);
        if ((k.w >> 21) == pref0) atomicAdd(&sh[(k.w >> 10) & 0x7FFu], 1u);
    }
    if (bid == 0) {
        for (int a = Atail + tid; a < A; a += NTHR) {
            unsigned k = g_key[a];
            if ((k >> 21) == pref0) atomicAdd(&sh[(k >> 10) & 0x7FFu], 1u);
        }
    }
    __syncthreads();
    for (int i = tid; i < 2048; i += NTHR) {
        unsigned v = sh[i];
        if (v) atomicAdd(&g_hist1[i], v);
    }
}

// ======= K3: select0+1 -> 22-bit prefix; sweep -> hist2 (low 10 bits) ======
__global__ void __launch_bounds__(NTHR, 1)
k_sweep2(int A) {
    __shared__ unsigned s_wsm[32];
    __shared__ int s_sel;
    __shared__ unsigned s_dig, s_krem;
    __shared__ unsigned sh[1024];
    int tid = threadIdx.x, bid = blockIdx.x;
    block_select(g_hist0, 2048, KTOP, s_wsm, &s_sel, &s_dig, &s_krem);
    unsigned pref0 = s_dig, krem1 = s_krem;
    block_select(g_hist1, 2048, krem1, s_wsm, &s_sel, &s_dig, &s_krem);
    unsigned pref21 = (pref0 << 11) | s_dig;
    for (int i = tid; i < 1024; i += NTHR) sh[i] = 0;
    __syncthreads();
    int A4 = A >> 2, Atail = A4 << 2;
    const uint4* kp = (const uint4*)g_key;
    for (int i = bid * NTHR + tid; i < A4; i += NBLK * NTHR) {
        uint4 k = kp[i];
        if ((k.x >> 10) == pref21) atomicAdd(&sh[k.x & 0x3FFu], 1u);
        if ((k.y >> 10) == pref21) atomicAdd(&sh[k.y & 0x3FFu], 1u);
        if ((k.z >> 10) == pref21) atomicAdd(&sh[k.z & 0x3FFu], 1u);
        if ((k.w >> 10) == pref21) atomicAdd(&sh[k.w & 0x3FFu], 1u);
    }
    if (bid == 0) {
        for (int a = Atail + tid; a < A; a += NTHR) {
            unsigned k = g_key[a];
            if ((k >> 10) == pref21) atomicAdd(&sh[k & 0x3FFu], 1u);
        }
    }
    __syncthreads();
    for (int i = tid; i < 1024; i += NTHR) {
        unsigned v = sh[i];
        if (v) atomicAdd(&g_hist2[i], v);
    }
}

// ======= K4: selects -> full 32-bit pivot; compact cands + index ties ======
__global__ void __launch_bounds__(NTHR, 1)
k_compact(int A) {
    __shared__ unsigned s_wsm[32];
    __shared__ int s_sel;
    __shared__ unsigned s_dig, s_krem;
    int tid = threadIdx.x, bid = blockIdx.x;
    block_select(g_hist0, 2048, KTOP, s_wsm, &s_sel, &s_dig, &s_krem);
    unsigned pref0 = s_dig, krem1 = s_krem;
    block_select(g_hist1, 2048, krem1, s_wsm, &s_sel, &s_dig, &s_krem);
    unsigned pref21 = (pref0 << 11) | s_dig;
    unsigned krem2 = s_krem;
    block_select(g_hist2, 1024, krem2, s_wsm, &s_sel, &s_dig, &s_krem);
    unsigned pivot = (pref21 << 10) | s_dig;
    int A4 = A >> 2, Atail = A4 << 2;
    const uint4* kp = (const uint4*)g_key;
    for (int i = bid * NTHR + tid; i < A4; i += NBLK * NTHR) {
        uint4 kv = kp[i];
        unsigned base = (unsigned)(i << 2);
        #pragma unroll
        for (int c = 0; c < 4; ++c) {
            unsigned k = (c == 0) ? kv.x : (c == 1) ? kv.y : (c == 2) ? kv.z : kv.w;
            unsigned a = base + (unsigned)c;
            if (k > pivot) {
                int p = atomicAdd(&g_candCount, 1);
                g_cand[p] = ((unsigned long long)k << 32) | (0xFFFFFFFFu - a);
            } else if (k == pivot) {
                int t2 = atomicAdd(&g_tieCount, 1);
                g_ties[t2] = a;
            }
        }
    }
    if (bid == 0) {
        for (int a = Atail + tid; a < A; a += NTHR) {
            unsigned k = g_key[a];
            if (k > pivot) {
                int p = atomicAdd(&g_candCount, 1);
                g_cand[p] = ((unsigned long long)k << 32) | (0xFFFFFFFFu - (unsigned)a);
            } else if (k == pivot) {
                int t2 = atomicAdd(&g_tieCount, 1);
                g_ties[t2] = (unsigned)a;
            }
        }
    }
}

// ======= K5 (1 block): tie-fill + bitonic sort + decode + cleanup ==========
__global__ void __launch_bounds__(NTHR, 1)
k_prep(const float* __restrict__ reg, const float* __restrict__ anc,
       const int* __restrict__ pih, const int* __restrict__ piw) {
    __shared__ unsigned long long scand[KPAD];    // 8KB
    __shared__ unsigned sties[2048];              // 8KB
    int tid = threadIdx.x;
    int CA = g_candCount, T = g_tieCount;
    int need = KTOP - CA;
    // recover pivot from any tie's key (ties exist iff need>0)
    scand[tid] = (tid < CA) ? g_cand[tid]
               : ((tid >= KTOP) ? (unsigned long long)(KPAD - tid) : 0ULL);
    if (need > 0) {
        unsigned pivKeyIdx = g_ties[0];
        unsigned long long pivKey = ((unsigned long long)g_key[pivKeyIdx]) << 32;
        if (T <= 2048) {
            if (tid < T) sties[tid] = g_ties[tid];
            if (tid + 1024 < T) sties[tid + 1024] = g_ties[tid + 1024];
            __syncthreads();
            for (int t = tid; t < T; t += NTHR) {
                unsigned v = sties[t];
                int rank = 0;
                for (int i = 0; i < T; ++i) rank += (sties[i] < v);
                if (rank < need) scand[CA + rank] = pivKey | (0xFFFFFFFFu - v);
            }
        } else {
            // fallback: sequential min-index extraction (rare)
            unsigned prev = 0; bool first = true;
            for (int r2 = 0; r2 < need; ++r2) {
                unsigned lm = 0xFFFFFFFFu;
                for (int i = tid; i < T; i += NTHR) {
                    unsigned v = g_ties[i];
                    if ((first || v > prev) && v < lm) lm = v;
                }
                sties[tid] = lm;
                __syncthreads();
                for (int st = 512; st; st >>= 1) {
                    if (tid < st) sties[tid] = min(sties[tid], sties[tid + st]);
                    __syncthreads();
                }
                prev = sties[0]; first = false;
                if (tid == 0) scand[CA + r2] = pivKey | (0xFFFFFFFFu - prev);
                __syncthreads();
            }
        }
    }
    __syncthreads();
    // bitonic sort descending (score desc, index asc) -> rank == position
    for (int k = 2; k <= 1024; k <<= 1)
        for (int j = k >> 1; j > 0; j >>= 1) {
            int ixj = tid ^ j;
            if (ixj > tid) {
                unsigned long long a = scand[tid], b = scand[ixj];
                bool up = ((tid & k) == 0);
                if (up ? (a < b) : (a > b)) { scand[tid] = b; scand[ixj] = a; }
            }
            __syncthreads();
        }
    unsigned long long ck = scand[tid];
    float score; float4 box; unsigned idx = 0;
    if (ck >= (1ULL << 32)) {
        unsigned key = (unsigned)(ck >> 32);
        idx = 0xFFFFFFFFu - (unsigned)(ck & 0xFFFFFFFFu);
        score = key2f(key);
        float4 a4 = ((const float4*)anc)[idx];
        float4 r4 = ((const float4*)reg)[idx];
        float aw = a4.z - a4.x, ah = a4.w - a4.y;
        float acx = a4.x + 0.5f * aw, acy = a4.y + 0.5f * ah;
        float pcx = acx + (r4.x * 0.1f) * aw;
        float pcy = acy + (r4.y * 0.1f) * ah;
        float pw = expf(r4.z * 0.2f) * aw;
        float ph = expf(r4.w * 0.2f) * ah;
        float W = (float)(*piw);
        float H = (float)(*pih);
        box.x = fminf(fmaxf(pcx - 0.5f * pw, 0.f), W);
        box.y = fminf(fmaxf(pcy - 0.5f * ph, 0.f), H);
        box.z = fminf(fmaxf(pcx + 0.5f * pw, 0.f), W);
        box.w = fminf(fmaxf(pcy + 0.5f * ph, 0.f), H);
    } else {
        score = -1.0f;
        box.x = box.y = box.z = box.w = 0.f;
    }
    g_rscore[tid] = score;
    g_ridx[tid] = idx;
    ((float4*)g_rbox)[tid] = box;
    // cleanup for next graph replay (single block: race-free)
    for (int i = tid; i < 2048; i += NTHR) { g_hist0[i] = 0; g_hist1[i] = 0; }
    for (int i = tid; i < 1024; i += NTHR) g_hist2[i] = 0;
    if (tid == 0) { g_candCount = 0; g_tieCount = 0; }
}

// ======= K6: triangle IoU suppression mask (rank space) ====================
__global__ void __launch_bounds__(NTHR, 1)
k_mask() {
    __shared__ float4 sbox[KPAD];
    __shared__ float  sarea[KPAD];
    int tid = threadIdx.x, bid = blockIdx.x;
    float4 b0 = ((const float4*)g_rbox)[tid];
    sbox[tid] = b0;
    sarea[tid] = fmaxf(b0.z - b0.x, 0.f) * fmaxf(b0.w - b0.y, 0.f);
    __syncthreads();
    float4 cb = sbox[tid];
    float  ca = sarea[tid];
    for (int r = bid; r < KPAD; r += NBLK) {
        bool sup = false;
        if (tid > r) {
            float4 rb = sbox[r];
            float  ra = sarea[r];
            float xx1 = fmaxf(rb.x, cb.x);
            float yy1 = fmaxf(rb.y, cb.y);
            float xx2 = fminf(rb.z, cb.z);
            float yy2 = fminf(rb.w, cb.w);
            float inter = fmaxf(xx2 - xx1, 0.f) * fmaxf(yy2 - yy1, 0.f);
            float denom = ra + ca - inter + 1e-8f;
            sup = inter > IOU_THRESH * denom;
        }
        unsigned ball = __ballot_sync(0xFFFFFFFFu, sup);
        if ((tid & 31) == 0) g_maskR[r * 32 + (tid >> 5)] = ball;
    }
}

// ======= K7 (1 block): NMS scan + final outputs ============================
__global__ void __launch_bounds__(NTHR, 1)
k_nms(const float* __restrict__ cls, float* __restrict__ out, int C) {
    extern __shared__ unsigned char dsm[];
    __shared__ int s_dc;
    __shared__ int s_det[128];
    int tid = threadIdx.x;
    unsigned* smask = (unsigned*)dsm;
    {
        const uint4* gm = (const uint4*)g_maskR;
        uint4* sm4 = (uint4*)smask;
        for (int i = tid; i < KPAD * 8; i += NTHR) sm4[i] = gm[i];
    }
    int myvalid = (g_rscore[tid] > SCORE_THRESH) ? 1 : 0;
    int nvalid = __syncthreads_count(myvalid);   // valid = rank prefix
    if (tid < 32) {
        int base = tid * 32;
        unsigned alive;
        if (nvalid >= base + 32)      alive = 0xFFFFFFFFu;
        else if (nvalid <= base)      alive = 0u;
        else                          alive = (1u << (nvalid - base)) - 1u;
        unsigned rem = 0;
        int dc = 0;
        while (dc < MAXDET) {
            unsigned av = alive & ~rem;
            unsigned ball = __ballot_sync(0xFFFFFFFFu, av != 0u);
            if (!ball) break;
            int grp = __ffs(ball) - 1;
            unsigned gav = __shfl_sync(0xFFFFFFFFu, av, grp);
            int b = __ffs(gav) - 1;
            int rank = (grp << 5) + b;
            if (tid == 0) s_det[dc] = rank;
            dc++;
            if (tid == grp) alive &= ~(1u << b);
            rem |= smask[rank * 32 + tid];
        }
        if (tid == 0) s_dc = dc;
    }
    __syncthreads();
    int dc = s_dc;
    int lane = tid & 31;
    int w = tid >> 5;
    for (int d = w; d < MAXDET; d += 32) {
        if (d < dc) {
            int rank = s_det[d];
            unsigned idx = g_ridx[rank];
            const float* row = cls + (size_t)idx * C;
            float bv = -3.402823466e38f; int bi = 0;
            for (int c = lane; c < C; c += 32) {
                float v = row[c];
                if (v > bv) { bv = v; bi = c; }
            }
            #pragma unroll
            for (int o = 16; o; o >>= 1) {
                float ov = __shfl_down_sync(0xFFFFFFFFu, bv, o);
                int   oi = __shfl_down_sync(0xFFFFFFFFu, bi, o);
                if (ov > bv || (ov == bv && oi < bi)) { bv = ov; bi = oi; }
            }
            if (lane == 0) {
                out[d] = g_rscore[rank];
                out[100 + d] = (float)bi;
                out[200 + 4 * d + 0] = g_rbox[4 * rank + 0];
                out[200 + 4 * d + 1] = g_rbox[4 * rank + 1];
                out[200 + 4 * d + 2] = g_rbox[4 * rank + 2];
                out[200 + 4 * d + 3] = g_rbox[4 * rank + 3];
            }
        } else if (lane == 0) {
            out[d] = 0.0f;
            out[100 + d] = -1.0f;
            out[200 + 4 * d + 0] = 0.0f; out[200 + 4 * d + 1] = 0.0f;
            out[200 + 4 * d + 2] = 0.0f; out[200 + 4 * d + 3] = 0.0f;
        }
    }
}

// ---------------- host launcher ----------------
extern "C" void kernel_launch(void* const* d_in, const int* in_sizes, int n_in,
                              void* d_out, int out_size) {
    const float* cls = (const float*)d_in[0];
    const float* reg = (const float*)d_in[1];
    const float* anc = (const float*)d_in[2];
    const int* ih = (const int*)d_in[3];
    const int* iw = (const int*)d_in[4];

    int A = in_sizes[1] / 4;
    int C = (A > 0) ? (in_sizes[0] / A) : 80;
    float* out = (float*)d_out;
    (void)out_size; (void)n_in;

    cudaFuncSetAttribute(k_nms, cudaFuncAttributeMaxDynamicSharedMemorySize, DSMEM_NMS);

    k_score<<<1184, 256>>>(cls, A, C);
    k_sweep1<<<NBLK, NTHR>>>(A);
    k_sweep2<<<NBLK, NTHR>>>(A);
    k_compact<<<NBLK, NTHR>>>(A);
    k_prep<<<1, NTHR>>>(reg, anc, ih, iw);
    k_mask<<<NBLK, NTHR>>>();
    k_nms<<<1, NTHR, DSMEM_NMS>>>(cls, out, C);
}